// round 7
// baseline (speedup 1.0000x reference)
#include <cuda_runtime.h>
#include <math.h>

#define C_DIM 256
#define ROWS  16          // rows (points) per warp
#define MAX_B 1024

__device__ int   d_off[MAX_B + 1];
__device__ float d_mean[MAX_B * 3];
// Quadratic-form coefficients for analytic LN1 stats:
// [0..3]  = Sw0, Sw1, Sw2, Sb
// [4..6]  = S w0^2, S w1^2, S w2^2
// [7..9]  = S w0w1, S w0w2, S w1w2
// [10..12]= S w0b,  S w1b,  S w2b
// [13]    = S b^2
__device__ float d_qc[14];

__device__ __forceinline__ void warp_red2(float& a, float& b) {
#pragma unroll
    for (int o = 16; o; o >>= 1) {
        a += __shfl_xor_sync(0xffffffffu, a, o);
        b += __shfl_xor_sync(0xffffffffu, b, o);
    }
}

// ---------------------------------------------------------------------------
// Kernel 1: per-scene mean of coords + exclusive-prefix offsets of lengths.
// Auto-detects int32 vs int64 lengths via sum==N check.
// ---------------------------------------------------------------------------
__global__ void scene_stats_kernel(const float* __restrict__ coord,
                                   const void* __restrict__ lengths_raw,
                                   int N, int B) {
    int b = blockIdx.x;
    __shared__ long long sh_start, sh_len;
    if (threadIdx.x == 0) {
        const int* i32 = (const int*)lengths_raw;
        long long sum32 = 0;
        for (int k = 0; k < B; k++) sum32 += (long long)i32[k];
        bool is64 = (sum32 != (long long)N);
        const long long* i64 = (const long long*)lengths_raw;
        long long start = 0;
        for (int k = 0; k < b; k++)
            start += is64 ? i64[k] : (long long)i32[k];
        long long len = is64 ? i64[b] : (long long)i32[b];
        sh_start = start;
        sh_len   = len;
        d_off[b] = (int)start;
        if (b == B - 1) d_off[B] = (int)(start + len);
    }
    __syncthreads();
    long long start = sh_start, len = sh_len;

    float sx = 0.f, sy = 0.f, sz = 0.f;
    for (long long t = threadIdx.x; t < len; t += blockDim.x) {
        const float* p = coord + (start + t) * 3;
        sx += p[0]; sy += p[1]; sz += p[2];
    }
#pragma unroll
    for (int o = 16; o; o >>= 1) {
        sx += __shfl_xor_sync(0xffffffffu, sx, o);
        sy += __shfl_xor_sync(0xffffffffu, sy, o);
        sz += __shfl_xor_sync(0xffffffffu, sz, o);
    }
    __shared__ float red[32][3];
    int w = threadIdx.x >> 5, l = threadIdx.x & 31;
    if (l == 0) { red[w][0] = sx; red[w][1] = sy; red[w][2] = sz; }
    __syncthreads();
    if (threadIdx.x == 0) {
        float ax = 0.f, ay = 0.f, az = 0.f;
        int nw = (blockDim.x + 31) >> 5;
        for (int k = 0; k < nw; k++) { ax += red[k][0]; ay += red[k][1]; az += red[k][2]; }
        long long d = len > 0 ? len : 1;
        float inv = 1.0f / (float)d;
        d_mean[b * 3 + 0] = ax * inv;
        d_mean[b * 3 + 1] = ay * inv;
        d_mean[b * 3 + 2] = az * inv;
    }
}

// ---------------------------------------------------------------------------
// Kernel 1b: precompute the 14 quadratic-form coefficients (one block).
// Double accumulation in the final stage for determinism + accuracy.
// ---------------------------------------------------------------------------
__global__ void qcoef_kernel(const float* __restrict__ w_xyz,
                             const float* __restrict__ b_xyz) {
    int c = threadIdx.x;               // 256 threads, one channel each
    float w0 = w_xyz[c];
    float w1 = w_xyz[C_DIM + c];
    float w2 = w_xyz[2 * C_DIM + c];
    float bb = b_xyz[c];
    float loc[14] = { w0, w1, w2, bb,
                      w0 * w0, w1 * w1, w2 * w2,
                      w0 * w1, w0 * w2, w1 * w2,
                      w0 * bb, w1 * bb, w2 * bb,
                      bb * bb };
#pragma unroll
    for (int k = 0; k < 14; k++)
#pragma unroll
        for (int o = 16; o; o >>= 1)
            loc[k] += __shfl_xor_sync(0xffffffffu, loc[k], o);
    __shared__ float sh[8][14];
    int w = threadIdx.x >> 5, l = threadIdx.x & 31;
    if (l == 0)
#pragma unroll
        for (int k = 0; k < 14; k++) sh[w][k] = loc[k];
    __syncthreads();
    if (threadIdx.x == 0) {
#pragma unroll
        for (int k = 0; k < 14; k++) {
            double s = 0.0;
            for (int ww = 0; ww < 8; ww++) s += (double)sh[ww][k];
            d_qc[k] = (float)s;
        }
    }
}

// ---------------------------------------------------------------------------
// Kernel 2: fully fused. One warp per point-row, 8 channels per lane.
// LN1 statistics come from the analytic quadratic form (no warp reduction);
// only LN2 needs a shuffle-tree reduction.
// ---------------------------------------------------------------------------
__global__ void __launch_bounds__(256, 2)
fused_xcpe_kernel(const float* __restrict__ feat,
                  const float* __restrict__ coord,
                  const float* __restrict__ w_xyz,  const float* __restrict__ b_xyz,
                  const float* __restrict__ g1,     const float* __restrict__ be1,
                  const float* __restrict__ w_conv, const float* __restrict__ b_conv,
                  const float* __restrict__ g2,     const float* __restrict__ be2,
                  float* __restrict__ out, int N) {
    // Shared: wx0 | wx1 | wx2 | bx | g1 | be1  (6 KB) + quad coefficients.
    __shared__ float sp[6 * C_DIM];
    __shared__ float sqc[14];
    for (int k = threadIdx.x; k < 6 * C_DIM; k += blockDim.x) {
        const float* src;
        int a = k >> 8, c = k & 255;
        switch (a) {
            case 0: src = w_xyz;              break;
            case 1: src = w_xyz + C_DIM;      break;
            case 2: src = w_xyz + 2 * C_DIM;  break;
            case 3: src = b_xyz;              break;
            case 4: src = g1;                 break;
            default: src = be1;               break;
        }
        sp[k] = src[c];
    }
    if (threadIdx.x < 14) sqc[threadIdx.x] = d_qc[threadIdx.x];
    __syncthreads();

    const int lane = threadIdx.x & 31;
    const int warp = blockIdx.x * (blockDim.x >> 5) + (threadIdx.x >> 5);
    int r0 = warp * ROWS;
    if (r0 >= N) return;
    int r1 = min(r0 + ROWS, N);
    const int c0 = lane * 8;

    // Phase-2 params in registers.
    float g2v[8], b2v[8], bcv[8], wc0[8], wc1[8], wc2[8];
#define LD8(dst, ptr)                                          \
    {                                                          \
        float4 t0 = *(const float4*)((ptr) + c0);              \
        float4 t1 = *(const float4*)((ptr) + c0 + 4);          \
        dst[0] = t0.x; dst[1] = t0.y; dst[2] = t0.z; dst[3] = t0.w; \
        dst[4] = t1.x; dst[5] = t1.y; dst[6] = t1.z; dst[7] = t1.w; \
    }
    LD8(g2v, g2);  LD8(b2v, be2);
    LD8(bcv, b_conv);
#pragma unroll
    for (int j = 0; j < 8; j++) {
        wc0[j] = w_conv[(c0 + j) * 3 + 0];
        wc1[j] = w_conv[(c0 + j) * 3 + 1];
        wc2[j] = w_conv[(c0 + j) * 3 + 2];
    }

    // Scene bounds for row r0.
    int s = 0;
    while (r0 >= d_off[s + 1]) s++;
    int sb = d_off[s], se = d_off[s + 1];

    float fA[8], fB[8], fC[8], feB[8], feC[8];

    // f(i) = feat(i) + gelu(LN1(xyz_c(i) @ W + b)); LN1 stats are analytic.
    auto compute_f = [&](int i, int sc, float* f, float* fe) {
        float x = coord[3 * i + 0] - d_mean[sc * 3 + 0];
        float y = coord[3 * i + 1] - d_mean[sc * 3 + 1];
        float z = coord[3 * i + 2] - d_mean[sc * 3 + 2];
        // Analytic LN1 statistics (uniform across the warp).
        float mu = fmaf(x, sqc[0], fmaf(y, sqc[1], fmaf(z, sqc[2], sqc[3]))) * (1.0f / C_DIM);
        float q  = fmaf(x * x, sqc[4],
                   fmaf(y * y, sqc[5],
                   fmaf(z * z, sqc[6], sqc[13])));
        float qx = fmaf(x * y, sqc[7],
                   fmaf(x * z, sqc[8],
                   fmaf(y * z, sqc[9],
                   fmaf(x, sqc[10], fmaf(y, sqc[11], z * sqc[12])))));
        float var = fmaf(2.0f, qx, q) * (1.0f / C_DIM) - mu * mu;
        float rs  = rsqrtf(var + 1e-5f);

        const float* frow = feat + (size_t)i * C_DIM + c0;
        float4 t0 = *(const float4*)frow;
        float4 t1 = *(const float4*)(frow + 4);
        fe[0] = t0.x; fe[1] = t0.y; fe[2] = t0.z; fe[3] = t0.w;
        fe[4] = t1.x; fe[5] = t1.y; fe[6] = t1.z; fe[7] = t1.w;
#pragma unroll
        for (int j = 0; j < 8; j++) {
            float v = fmaf(x, sp[0 * C_DIM + c0 + j],
                      fmaf(y, sp[1 * C_DIM + c0 + j],
                      fmaf(z, sp[2 * C_DIM + c0 + j], sp[3 * C_DIM + c0 + j])));
            float t  = fmaf((v - mu) * rs, sp[4 * C_DIM + c0 + j], sp[5 * C_DIM + c0 + j]);
            float gl = 0.5f * t * (1.0f + erff(t * 0.7071067811865475f));
            f[j] = fe[j] + gl;
        }
    };

    // Prologue.
    if (r0 > 0) {
        float dummy[8];
        compute_f(r0 - 1, s, fA, dummy);
    } else {
#pragma unroll
        for (int j = 0; j < 8; j++) fA[j] = 0.f;
    }
    compute_f(r0, s, fB, feB);

    for (int i = r0; i < r1; i++) {
        int ip = i + 1;
        int sn = s, sbn = sb, sen = se;
        if (ip < N) {
            if (ip >= se) { sn = s + 1; sbn = se; sen = d_off[sn + 1]; }
            compute_f(ip, sn, fC, feC);
        } else {
#pragma unroll
            for (int j = 0; j < 8; j++) { fC[j] = 0.f; feC[j] = 0.f; }
        }
        float mp = (i > sb)  ? 1.f : 0.f;
        float mn = (ip < se) ? 1.f : 0.f;

        float h[8];
        float sm = 0.f, sq = 0.f;
#pragma unroll
        for (int j = 0; j < 8; j++) {
            float cv = fmaf(wc1[j], fB[j], bcv[j]);
            cv = fmaf(wc0[j], mp * fA[j], cv);
            cv = fmaf(wc2[j], mn * fC[j], cv);
            float hh = feB[j] + cv;
            h[j] = hh;
            sm += hh;
            sq = fmaf(hh, hh, sq);
        }
        warp_red2(sm, sq);
        float mu  = sm * (1.0f / C_DIM);
        float var = sq * (1.0f / C_DIM) - mu * mu;
        float rs  = rsqrtf(var + 1e-5f);

        float* orow = out + (size_t)i * C_DIM + c0;
        float4 o0, o1;
        o0.x = fmaf((h[0] - mu) * rs, g2v[0], b2v[0]);
        o0.y = fmaf((h[1] - mu) * rs, g2v[1], b2v[1]);
        o0.z = fmaf((h[2] - mu) * rs, g2v[2], b2v[2]);
        o0.w = fmaf((h[3] - mu) * rs, g2v[3], b2v[3]);
        o1.x = fmaf((h[4] - mu) * rs, g2v[4], b2v[4]);
        o1.y = fmaf((h[5] - mu) * rs, g2v[5], b2v[5]);
        o1.z = fmaf((h[6] - mu) * rs, g2v[6], b2v[6]);
        o1.w = fmaf((h[7] - mu) * rs, g2v[7], b2v[7]);
        *(float4*)orow       = o0;
        *(float4*)(orow + 4) = o1;

#pragma unroll
        for (int j = 0; j < 8; j++) { fA[j] = fB[j]; fB[j] = fC[j]; feB[j] = feC[j]; }
        s = sn; sb = sbn; se = sen;
    }
}

// ---------------------------------------------------------------------------
extern "C" void kernel_launch(void* const* d_in, const int* in_sizes, int n_in,
                              void* d_out, int out_size) {
    const float* feat   = (const float*)d_in[0];
    const float* coord  = (const float*)d_in[1];
    const void*  lens   = d_in[2];
    const float* w_xyz  = (const float*)d_in[3];
    const float* b_xyz  = (const float*)d_in[4];
    const float* g1     = (const float*)d_in[5];
    const float* be1    = (const float*)d_in[6];
    const float* w_conv = (const float*)d_in[7];
    const float* b_conv = (const float*)d_in[8];
    const float* g2     = (const float*)d_in[9];
    const float* be2    = (const float*)d_in[10];

    int N = in_sizes[0] / C_DIM;
    int B = in_sizes[2];
    if (B > MAX_B) B = MAX_B;

    scene_stats_kernel<<<B, 1024>>>(coord, lens, N, B);
    qcoef_kernel<<<1, 256>>>(w_xyz, b_xyz);

    int warps  = (N + ROWS - 1) / ROWS;
    int blocks = (warps + 7) / 8;
    fused_xcpe_kernel<<<blocks, 256>>>(feat, coord, w_xyz, b_xyz, g1, be1,
                                       w_conv, b_conv, g2, be2,
                                       (float*)d_out, N);
}

// round 8
// speedup vs baseline: 1.7479x; 1.7479x over previous
#include <cuda_runtime.h>
#include <math.h>

#define C_DIM 256
#define ROWS  16          // rows (points) per warp (even; pairing step = 2)
#define MAX_B 1024

__device__ int   d_off[MAX_B + 1];
__device__ float d_mean[MAX_B * 3];
// Quadratic-form coefficients for analytic LN1 stats:
// [0..3]=Sw0,Sw1,Sw2,Sb  [4..6]=Sw0^2,Sw1^2,Sw2^2
// [7..9]=Sw0w1,Sw0w2,Sw1w2  [10..12]=Sw0b,Sw1b,Sw2b  [13]=Sb^2
__device__ float d_qc[14];

__device__ __forceinline__ void warp_red2(float& a, float& b) {
#pragma unroll
    for (int o = 16; o; o >>= 1) {
        a += __shfl_xor_sync(0xffffffffu, a, o);
        b += __shfl_xor_sync(0xffffffffu, b, o);
    }
}

// ---------------------------------------------------------------------------
// Prep kernel: blocks 0..B-1 compute per-scene coord means + offsets;
// block B computes the 14 quadratic-form coefficients. One launch.
// ---------------------------------------------------------------------------
__global__ void prep_kernel(const float* __restrict__ coord,
                            const void* __restrict__ lengths_raw,
                            const float* __restrict__ w_xyz,
                            const float* __restrict__ b_xyz,
                            int N, int B) {
    if ((int)blockIdx.x == B) {
        // ---- quadratic coefficients (first 256 threads) ----
        if (threadIdx.x < 256) {
            int c = threadIdx.x;
            float w0 = w_xyz[c];
            float w1 = w_xyz[C_DIM + c];
            float w2 = w_xyz[2 * C_DIM + c];
            float bb = b_xyz[c];
            float loc[14] = { w0, w1, w2, bb,
                              w0 * w0, w1 * w1, w2 * w2,
                              w0 * w1, w0 * w2, w1 * w2,
                              w0 * bb, w1 * bb, w2 * bb,
                              bb * bb };
#pragma unroll
            for (int k = 0; k < 14; k++)
#pragma unroll
                for (int o = 16; o; o >>= 1)
                    loc[k] += __shfl_xor_sync(0xffffffffu, loc[k], o);
            __shared__ float sh[8][14];
            int w = threadIdx.x >> 5, l = threadIdx.x & 31;
            if (l == 0)
#pragma unroll
                for (int k = 0; k < 14; k++) sh[w][k] = loc[k];
            __syncthreads();
            if (threadIdx.x == 0) {
#pragma unroll
                for (int k = 0; k < 14; k++) {
                    double s = 0.0;
                    for (int ww = 0; ww < 8; ww++) s += (double)sh[ww][k];
                    d_qc[k] = (float)s;
                }
            }
        }
        return;
    }

    // ---- per-scene stats (blocks 0..B-1) ----
    int b = blockIdx.x;
    __shared__ long long sh_start, sh_len;
    if (threadIdx.x == 0) {
        const int* i32 = (const int*)lengths_raw;
        long long sum32 = 0;
        for (int k = 0; k < B; k++) sum32 += (long long)i32[k];
        bool is64 = (sum32 != (long long)N);
        const long long* i64 = (const long long*)lengths_raw;
        long long start = 0;
        for (int k = 0; k < b; k++)
            start += is64 ? i64[k] : (long long)i32[k];
        long long len = is64 ? i64[b] : (long long)i32[b];
        sh_start = start;
        sh_len   = len;
        d_off[b] = (int)start;
        if (b == B - 1) d_off[B] = (int)(start + len);
    }
    __syncthreads();
    long long start = sh_start, len = sh_len;

    float sx = 0.f, sy = 0.f, sz = 0.f;
    for (long long t = threadIdx.x; t < len; t += blockDim.x) {
        const float* p = coord + (start + t) * 3;
        sx += p[0]; sy += p[1]; sz += p[2];
    }
#pragma unroll
    for (int o = 16; o; o >>= 1) {
        sx += __shfl_xor_sync(0xffffffffu, sx, o);
        sy += __shfl_xor_sync(0xffffffffu, sy, o);
        sz += __shfl_xor_sync(0xffffffffu, sz, o);
    }
    __shared__ float red[32][3];
    int w = threadIdx.x >> 5, l = threadIdx.x & 31;
    if (l == 0) { red[w][0] = sx; red[w][1] = sy; red[w][2] = sz; }
    __syncthreads();
    if (threadIdx.x == 0) {
        float ax = 0.f, ay = 0.f, az = 0.f;
        int nw = (blockDim.x + 31) >> 5;
        for (int k = 0; k < nw; k++) { ax += red[k][0]; ay += red[k][1]; az += red[k][2]; }
        long long d = len > 0 ? len : 1;
        float inv = 1.0f / (float)d;
        d_mean[b * 3 + 0] = ax * inv;
        d_mean[b * 3 + 1] = ay * inv;
        d_mean[b * 3 + 2] = az * inv;
    }
}

// ---------------------------------------------------------------------------
// Fused kernel. One warp per point-row pair, 8 channels per lane.
// LN1 stats analytic (no reduction); rows processed two at a time for ILP
// on the erff chains and the LN2 shuffle reductions.
// ---------------------------------------------------------------------------
__global__ void __launch_bounds__(256, 2)
fused_xcpe_kernel(const float* __restrict__ feat,
                  const float* __restrict__ coord,
                  const float* __restrict__ w_xyz,  const float* __restrict__ b_xyz,
                  const float* __restrict__ g1,     const float* __restrict__ be1,
                  const float* __restrict__ w_conv, const float* __restrict__ b_conv,
                  const float* __restrict__ g2,     const float* __restrict__ be2,
                  float* __restrict__ out, int N) {
    // Shared params: wx0|wx1|wx2|bx|g1|be1|g2|be2 (8KB) + quad coefficients.
    __shared__ float sp[8 * C_DIM];
    __shared__ float sqc[14];
    for (int k = threadIdx.x; k < 8 * C_DIM; k += blockDim.x) {
        const float* src;
        int a = k >> 8, c = k & 255;
        switch (a) {
            case 0: src = w_xyz;              break;
            case 1: src = w_xyz + C_DIM;      break;
            case 2: src = w_xyz + 2 * C_DIM;  break;
            case 3: src = b_xyz;              break;
            case 4: src = g1;                 break;
            case 5: src = be1;                break;
            case 6: src = g2;                 break;
            default: src = be2;               break;
        }
        sp[k] = src[c];
    }
    if (threadIdx.x < 14) sqc[threadIdx.x] = d_qc[threadIdx.x];
    __syncthreads();

    const int lane = threadIdx.x & 31;
    const int warp = blockIdx.x * (blockDim.x >> 5) + (threadIdx.x >> 5);
    int r0 = warp * ROWS;
    if (r0 >= N) return;
    int r1 = min(r0 + ROWS, N);
    const int c0 = lane * 8;

    // Conv params in registers.
    float bcv[8], wc0[8], wc1[8], wc2[8];
    {
        float4 t0 = *(const float4*)(b_conv + c0);
        float4 t1 = *(const float4*)(b_conv + c0 + 4);
        bcv[0]=t0.x; bcv[1]=t0.y; bcv[2]=t0.z; bcv[3]=t0.w;
        bcv[4]=t1.x; bcv[5]=t1.y; bcv[6]=t1.z; bcv[7]=t1.w;
    }
#pragma unroll
    for (int j = 0; j < 8; j++) {
        wc0[j] = w_conv[(c0 + j) * 3 + 0];
        wc1[j] = w_conv[(c0 + j) * 3 + 1];
        wc2[j] = w_conv[(c0 + j) * 3 + 2];
    }

    // Scene of row r0.
    int s = 0;
    while (r0 >= d_off[s + 1]) s++;
    int sb = d_off[s], se = d_off[s + 1];

    float fA[8], fB[8], fC[8], fD[8];

    // f(i) = feat(i) + gelu(LN1(xyz_c(i) @ W + b)), analytic LN1 stats.
    // feat loads issued FIRST so LDG latency overlaps the stats math.
    auto compute_f = [&](int i, int sc, float* f) {
        const float* frow = feat + (size_t)i * C_DIM + c0;
        float4 t0 = *(const float4*)frow;
        float4 t1 = *(const float4*)(frow + 4);
        float x = coord[3 * i + 0] - d_mean[sc * 3 + 0];
        float y = coord[3 * i + 1] - d_mean[sc * 3 + 1];
        float z = coord[3 * i + 2] - d_mean[sc * 3 + 2];
        float mu = fmaf(x, sqc[0], fmaf(y, sqc[1], fmaf(z, sqc[2], sqc[3]))) * (1.0f / C_DIM);
        float q  = fmaf(x * x, sqc[4],
                   fmaf(y * y, sqc[5],
                   fmaf(z * z, sqc[6], sqc[13])));
        float qx = fmaf(x * y, sqc[7],
                   fmaf(x * z, sqc[8],
                   fmaf(y * z, sqc[9],
                   fmaf(x, sqc[10], fmaf(y, sqc[11], z * sqc[12])))));
        float var = fmaf(2.0f, qx, q) * (1.0f / C_DIM) - mu * mu;
        float rs  = rsqrtf(var + 1e-5f);
        float fe[8] = { t0.x, t0.y, t0.z, t0.w, t1.x, t1.y, t1.z, t1.w };
#pragma unroll
        for (int j = 0; j < 8; j++) {
            float v = fmaf(x, sp[0 * C_DIM + c0 + j],
                      fmaf(y, sp[1 * C_DIM + c0 + j],
                      fmaf(z, sp[2 * C_DIM + c0 + j], sp[3 * C_DIM + c0 + j])));
            float t  = fmaf((v - mu) * rs, sp[4 * C_DIM + c0 + j], sp[5 * C_DIM + c0 + j]);
            float gl = 0.5f * t * (1.0f + erff(t * 0.7071067811865475f));
            f[j] = fe[j] + gl;
        }
    };

    // Phase 2 for one row: conv + residual + LN2 + store. feat re-read (L1 hit).
    auto phase2 = [&](int i, const float* fp, const float* fc, const float* fn,
                      bool hasP, bool hasN) {
        const float* frow = feat + (size_t)i * C_DIM + c0;
        float4 e0 = *(const float4*)frow;
        float4 e1 = *(const float4*)(frow + 4);
        float fe[8] = { e0.x, e0.y, e0.z, e0.w, e1.x, e1.y, e1.z, e1.w };
        float h[8];
        float sm = 0.f, sq = 0.f;
        if (hasP & hasN) {      // warp-uniform fast path (interior rows)
#pragma unroll
            for (int j = 0; j < 8; j++) {
                float cv = fmaf(wc0[j], fp[j],
                           fmaf(wc1[j], fc[j],
                           fmaf(wc2[j], fn[j], bcv[j])));
                float hh = fe[j] + cv;
                h[j] = hh; sm += hh; sq = fmaf(hh, hh, sq);
            }
        } else {
            float mp = hasP ? 1.f : 0.f, mn = hasN ? 1.f : 0.f;
#pragma unroll
            for (int j = 0; j < 8; j++) {
                float cv = fmaf(wc0[j], mp * fp[j],
                           fmaf(wc1[j], fc[j],
                           fmaf(wc2[j], mn * fn[j], bcv[j])));
                float hh = fe[j] + cv;
                h[j] = hh; sm += hh; sq = fmaf(hh, hh, sq);
            }
        }
        warp_red2(sm, sq);
        float mu  = sm * (1.0f / C_DIM);
        float var = sq * (1.0f / C_DIM) - mu * mu;
        float rs  = rsqrtf(var + 1e-5f);
        float* orow = out + (size_t)i * C_DIM + c0;
        float4 o0, o1;
        o0.x = fmaf((h[0] - mu) * rs, sp[6 * C_DIM + c0 + 0], sp[7 * C_DIM + c0 + 0]);
        o0.y = fmaf((h[1] - mu) * rs, sp[6 * C_DIM + c0 + 1], sp[7 * C_DIM + c0 + 1]);
        o0.z = fmaf((h[2] - mu) * rs, sp[6 * C_DIM + c0 + 2], sp[7 * C_DIM + c0 + 2]);
        o0.w = fmaf((h[3] - mu) * rs, sp[6 * C_DIM + c0 + 3], sp[7 * C_DIM + c0 + 3]);
        o1.x = fmaf((h[4] - mu) * rs, sp[6 * C_DIM + c0 + 4], sp[7 * C_DIM + c0 + 4]);
        o1.y = fmaf((h[5] - mu) * rs, sp[6 * C_DIM + c0 + 5], sp[7 * C_DIM + c0 + 5]);
        o1.z = fmaf((h[6] - mu) * rs, sp[6 * C_DIM + c0 + 6], sp[7 * C_DIM + c0 + 6]);
        o1.w = fmaf((h[7] - mu) * rs, sp[6 * C_DIM + c0 + 7], sp[7 * C_DIM + c0 + 7]);
        *(float4*)orow       = o0;
        *(float4*)(orow + 4) = o1;
    };

    // Prologue: fA = f(r0-1) (masked at scene start, so wrong-scene is fine),
    // fB = f(r0).
    if (r0 > 0) compute_f(r0 - 1, s, fA);
    else {
#pragma unroll
        for (int j = 0; j < 8; j++) fA[j] = 0.f;
    }
    compute_f(r0, s, fB);

    for (int i = r0; i < r1; i += 2) {
        int i1 = i + 1, i2 = i + 2;
        // Scenes of i1, i2.
        int s1 = s, sb1 = sb, se1 = se;
        if (i1 < N) { while (i1 >= se1) { s1++; sb1 = se1; se1 = d_off[s1 + 1]; } }
        int s2 = s1, sb2 = sb1, se2 = se1;
        if (i2 < N) { while (i2 >= se2) { s2++; sb2 = se2; se2 = d_off[s2 + 1]; } }

        // Two independent compute_f chains (ILP on erff + LDG).
        if (i1 < N) compute_f(i1, s1, fC);
        else {
#pragma unroll
            for (int j = 0; j < 8; j++) fC[j] = 0.f;
        }
        if (i2 < N) compute_f(i2, s2, fD);
        else {
#pragma unroll
            for (int j = 0; j < 8; j++) fD[j] = 0.f;
        }

        // Two independent LN2 chains.
        phase2(i,  fA, fB, fC, i  > sb,  i1 < se);
        phase2(i1, fB, fC, fD, i1 > sb1, i2 < se1);

        // Shift window by 2.
#pragma unroll
        for (int j = 0; j < 8; j++) { fA[j] = fC[j]; fB[j] = fD[j]; }
        s = s2; sb = sb2; se = se2;
    }
}

// ---------------------------------------------------------------------------
extern "C" void kernel_launch(void* const* d_in, const int* in_sizes, int n_in,
                              void* d_out, int out_size) {
    const float* feat   = (const float*)d_in[0];
    const float* coord  = (const float*)d_in[1];
    const void*  lens   = d_in[2];
    const float* w_xyz  = (const float*)d_in[3];
    const float* b_xyz  = (const float*)d_in[4];
    const float* g1     = (const float*)d_in[5];
    const float* be1    = (const float*)d_in[6];
    const float* w_conv = (const float*)d_in[7];
    const float* b_conv = (const float*)d_in[8];
    const float* g2     = (const float*)d_in[9];
    const float* be2    = (const float*)d_in[10];

    int N = in_sizes[0] / C_DIM;
    int B = in_sizes[2];
    if (B > MAX_B) B = MAX_B;

    prep_kernel<<<B + 1, 1024>>>(coord, lens, w_xyz, b_xyz, N, B);

    int warps  = (N + ROWS - 1) / ROWS;
    int blocks = (warps + 7) / 8;
    fused_xcpe_kernel<<<blocks, 256>>>(feat, coord, w_xyz, b_xyz, g1, be1,
                                       w_conv, b_conv, g2, be2,
                                       (float*)d_out, N);
}